// round 15
// baseline (speedup 1.0000x reference)
#include <cuda_runtime.h>
#include <cstdint>

#define TPB 256
#define TILE 256
#define NF 10
#define NC 64
#define NCOL 192
#define DK 5
#define INV_SQRT5 0.44721359549995793f

typedef uint32_t u32;

#define SA_STR 136   // A staging stride: af loads hit 32 distinct banks
#define SBV_STR 20   // per-lane B-frag block stride (float4-aligned, bank-clean)
#define SD_STR 35    // D-chunk stride: readback banks (3t+cc)%32 conflict-free

__device__ float g_K[NC * 8];   // K = posenc(centroids) @ Wk^T, stride 8

// ---------------------------------------------------------------------------
__global__ void precompute_K_kernel(const float* __restrict__ Wk,
                                    const float* __restrict__ centroids) {
    int c = threadIdx.x;
    if (c >= NC) return;
    float x0 = centroids[c * 3 + 0];
    float x1 = centroids[c * 3 + 1];
    float x2 = centroids[c * 3 + 2];
    float enc[60];
#pragma unroll
    for (int l = 0; l < NF; l++) {
        float f = (float)(1u << l);
        float s, co;
        sincosf(x0 * f, &s, &co); enc[l * 6 + 0] = s; enc[l * 6 + 3] = co;
        sincosf(x1 * f, &s, &co); enc[l * 6 + 1] = s; enc[l * 6 + 4] = co;
        sincosf(x2 * f, &s, &co); enc[l * 6 + 2] = s; enc[l * 6 + 5] = co;
    }
#pragma unroll
    for (int k = 0; k < 8; k++) {
        float a = 0.f;
        if (k < DK) {
#pragma unroll
            for (int e = 0; e < 60; e++) a += enc[e] * Wk[k * 60 + e];
        }
        g_K[c * 8 + k] = a;
    }
}

// ---------------------------------------------------------------------------
static __device__ __forceinline__ u32 to_tf32(float v) {
    u32 r;
    asm("cvt.rna.tf32.f32 %0, %1;" : "=r"(r) : "f"(v));
    return r;
}

static __device__ __forceinline__ void mma_tf32(float d[4], const u32 a[4],
                                                float b0, float b1) {
    asm volatile(
        "mma.sync.aligned.m16n8k8.row.col.f32.tf32.tf32.f32 "
        "{%0,%1,%2,%3}, {%4,%5,%6,%7}, {%8,%9}, {%0,%1,%2,%3};"
        : "+f"(d[0]), "+f"(d[1]), "+f"(d[2]), "+f"(d[3])
        : "r"(a[0]), "r"(a[1]), "r"(a[2]), "r"(a[3]),
          "r"(__float_as_uint(b0)), "r"(__float_as_uint(b1)));
}

static __device__ __forceinline__ float cluster_w(const float* sK,
                                                  const float q[DK], int c) {
    float4 k4 = *(const float4*)(sK + c * 8);
    float  k5 = sK[c * 8 + 4];
    float s = q[0] * k4.x + q[1] * k4.y + q[2] * k4.z + q[3] * k4.w + q[4] * k5;
    return __expf(s);
}

// ---------------------------------------------------------------------------
// Persistent kernel, 256 threads / 256-point tiles, 2 CTAs/SM.
//   rgb[256,192] = enc_tf32[256,64] @ LM_tf32[192,64]^T via mma.sync tf32.
//   B pre-packed per-(nt,lane) for LDS.128 fragment loads.
//   D staged in 32-col chunks; each thread reduces its OWN row, recomputing
//   softmax weights from registers; Z accumulated in the same pass.
//   kmeans exact fp32 via L2 reads (it IS the main output; TRADEOFF = 1).
// ---------------------------------------------------------------------------
__global__ __launch_bounds__(TPB, 2) void csa_kernel(
    const float* __restrict__ X,
    const int*   __restrict__ cids,
    const float* __restrict__ LM,
    const float* __restrict__ Wq,
    const float* __restrict__ Wv,
    float* __restrict__ out,
    int N, int mode)
{
    extern __shared__ float sm[];
    float* sBv = sm;                  // [24][32][20] packed B frags  15360 f
    float* sU  = sBv + 24 * 32 * SBV_STR; // A stage [64][136] / D chunk 8960 f
    float* sK  = sU + 8960;           // [64*8]                         512 f
    float* sWq = sK + NC * 8;         // [304]
    float* sWv = sWq + 304;           // [16]

    const int tid = threadIdx.x;

    // one-time: pack B fragments. For (nt, lane(g,r4)): 16 values =
    // float4 m=0..3 with components (b0[2m], b1[2m], b0[2m+1], b1[2m+1]),
    // where b0(ks) = B[n=nt*8+g][k=ks*8+r4], b1(ks) = same n, k+4.
    for (int i = tid; i < 24 * 32 * 16; i += TPB) {
        int nt = i >> 9, rem = i & 511;
        int lane = rem >> 4, idx = rem & 15;
        int m = idx >> 2, qq = idx & 3;
        int gg = lane >> 2, rr = lane & 3;
        int ks = 2 * m + (qq >> 1);
        int n = nt * 8 + gg;
        int k = ks * 8 + rr + 4 * (qq & 1);
        float v = (k < 60) ? LM[n * 60 + k] : 0.f;
        sBv[nt * (32 * SBV_STR) + lane * SBV_STR + idx] =
            __uint_as_float(to_tf32(v));
    }
    for (int i = tid; i < NC * 8; i += TPB) sK[i] = g_K[i];
    for (int i = tid; i < DK * 60; i += TPB) sWq[i] = Wq[i];
    if (tid < 9) sWv[tid] = Wv[tid];
    __syncthreads();

    const int lane = tid & 31;
    const int warp = tid >> 5;
    const int g = lane >> 2, r4 = lane & 3;
    const int half = tid >> 7;
    const int rb = (warp & 3) * 32 + g;
    const int wrow = warp * 32 + g;
    const int tiles = (N + TILE - 1) / TILE;

    for (int tile = blockIdx.x; tile < tiles; tile += gridDim.x) {
        int p = tile * TILE + tid;
        int pc = min(p, N - 1);

        // ---- prep: posenc (double-angle), q, exact kmeans via L2 ----
        float enc[64];
        {
            float x0 = X[3 * pc], x1 = X[3 * pc + 1], x2 = X[3 * pc + 2];
            float s0, c0, s1, c1, s2, c2;
            sincosf(x0, &s0, &c0);
            sincosf(x1, &s1, &c1);
            sincosf(x2, &s2, &c2);
#pragma unroll
            for (int l = 0; l < NF; l++) {
                enc[l * 6 + 0] = s0; enc[l * 6 + 1] = s1; enc[l * 6 + 2] = s2;
                enc[l * 6 + 3] = c0; enc[l * 6 + 4] = c1; enc[l * 6 + 5] = c2;
                if (l < NF - 1) {
                    float t, u;
                    t = s0 * c0; u = fmaf(c0, c0, -0.5f); s0 = t + t; c0 = u + u;
                    t = s1 * c1; u = fmaf(c1, c1, -0.5f); s1 = t + t; c1 = u + u;
                    t = s2 * c2; u = fmaf(c2, c2, -0.5f); s2 = t + t; c2 = u + u;
                }
            }
            enc[60] = enc[61] = enc[62] = enc[63] = 0.f;
        }

        float q[DK];
#pragma unroll
        for (int k = 0; k < DK; k++) {
            float a = 0.f;
            const float4* wp = (const float4*)(sWq + k * 60);
#pragma unroll
            for (int t = 0; t < 15; t++) {
                float4 w4 = wp[t];
                a += w4.x * enc[4 * t] + w4.y * enc[4 * t + 1]
                   + w4.z * enc[4 * t + 2] + w4.w * enc[4 * t + 3];
            }
            q[k] = a * INV_SQRT5;
        }

        {
            float km0 = 0.f, km1 = 0.f, km2 = 0.f;
            const float4* rp = (const float4*)(LM + 3 * (size_t)cids[pc] * 60);
#pragma unroll
            for (int t = 0; t < 15; t++) {
                float4 a = __ldg(rp + t);
                float4 b = __ldg(rp + 15 + t);
                float4 c4 = __ldg(rp + 30 + t);
                float e0 = enc[4 * t], e1 = enc[4 * t + 1];
                float e2 = enc[4 * t + 2], e3 = enc[4 * t + 3];
                km0 += a.x  * e0 + a.y  * e1 + a.z  * e2 + a.w  * e3;
                km1 += b.x  * e0 + b.y  * e1 + b.z  * e2 + b.w  * e3;
                km2 += c4.x * e0 + c4.y * e1 + c4.z * e2 + c4.w * e3;
            }
            if (p < N) {
                // TRADEOFF = 1.0 -> main out == kmeans_rgb exactly
                out[3 * p + 0] = km0;
                out[3 * p + 1] = km1;
                out[3 * p + 2] = km2;
                if (mode == 3) {
                    float* kmp = out + 3 * (size_t)N;
                    kmp[3 * p + 0] = km0;
                    kmp[3 * p + 1] = km1;
                    kmp[3 * p + 2] = km2;
                }
            }
        }

        // ---- two-phase A staging + fragment preload ----
        u32 af[2][8][4];
        if (half == 0) {
            int lrow = tid;
#pragma unroll
            for (int k = 0; k < 64; k++)
                sU[k * SA_STR + lrow] = __uint_as_float(to_tf32(enc[k]));
            __syncthreads();                                  // B1
#pragma unroll
            for (int ks = 0; ks < 8; ks++) {
                int kk = ks * 8 + r4;
                af[0][ks][0] = __float_as_uint(sU[kk * SA_STR + rb]);
                af[0][ks][1] = __float_as_uint(sU[kk * SA_STR + rb + 8]);
                af[0][ks][2] = __float_as_uint(sU[(kk + 4) * SA_STR + rb]);
                af[0][ks][3] = __float_as_uint(sU[(kk + 4) * SA_STR + rb + 8]);
                af[1][ks][0] = __float_as_uint(sU[kk * SA_STR + rb + 16]);
                af[1][ks][1] = __float_as_uint(sU[kk * SA_STR + rb + 24]);
                af[1][ks][2] = __float_as_uint(sU[(kk + 4) * SA_STR + rb + 16]);
                af[1][ks][3] = __float_as_uint(sU[(kk + 4) * SA_STR + rb + 24]);
            }
            __syncthreads();                                  // B2
            __syncthreads();                                  // B3
        } else {
            __syncthreads();                                  // B1
            __syncthreads();                                  // B2
            int lrow = tid - 128;
#pragma unroll
            for (int k = 0; k < 64; k++)
                sU[k * SA_STR + lrow] = __uint_as_float(to_tf32(enc[k]));
            __syncthreads();                                  // B3
#pragma unroll
            for (int ks = 0; ks < 8; ks++) {
                int kk = ks * 8 + r4;
                af[0][ks][0] = __float_as_uint(sU[kk * SA_STR + rb]);
                af[0][ks][1] = __float_as_uint(sU[kk * SA_STR + rb + 8]);
                af[0][ks][2] = __float_as_uint(sU[(kk + 4) * SA_STR + rb]);
                af[0][ks][3] = __float_as_uint(sU[(kk + 4) * SA_STR + rb + 8]);
                af[1][ks][0] = __float_as_uint(sU[kk * SA_STR + rb + 16]);
                af[1][ks][1] = __float_as_uint(sU[kk * SA_STR + rb + 24]);
                af[1][ks][2] = __float_as_uint(sU[(kk + 4) * SA_STR + rb + 16]);
                af[1][ks][3] = __float_as_uint(sU[(kk + 4) * SA_STR + rb + 24]);
            }
        }
        __syncthreads();                                      // B4: sU -> D chunk

        // ---- MMA + chunked own-row weighted reduce (Z fused) ----
        float acc0 = 0.f, acc1 = 0.f, acc2 = 0.f, Z = 0.f;
#pragma unroll
        for (int ct = 0; ct < 6; ct++) {
#pragma unroll
            for (int ntl = 0; ntl < 4; ntl++) {
                int nt = ct * 4 + ntl;
                float d0[4] = {0.f, 0.f, 0.f, 0.f};
                float d1[4] = {0.f, 0.f, 0.f, 0.f};
                const float4* bv =
                    (const float4*)(sBv + nt * (32 * SBV_STR) + lane * SBV_STR);
#pragma unroll
                for (int m = 0; m < 4; m++) {
                    float4 v = bv[m];                 // LDS.128, 4-wf optimal
                    mma_tf32(d0, af[0][2 * m],     v.x, v.y);
                    mma_tf32(d1, af[1][2 * m],     v.x, v.y);
                    mma_tf32(d0, af[0][2 * m + 1], v.z, v.w);
                    mma_tf32(d1, af[1][2 * m + 1], v.z, v.w);
                }
#pragma unroll
                for (int e = 0; e < 4; e++) {
                    int col = ntl * 8 + 2 * r4 + (e & 1);
                    int ro = 8 * (e >> 1);
                    sU[(wrow + ro) * SD_STR + col]      = d0[e];
                    sU[(wrow + 16 + ro) * SD_STR + col] = d1[e];
                }
            }
            __syncthreads();     // chunk staged

            const float* drow = sU + tid * SD_STR;
            float w = 0.f;
            int cl = -1;
#pragma unroll
            for (int cc = 0; cc < 32; cc++) {
                int gc = ct * 32 + cc;
                int c = gc / 3, j = gc - 3 * c;
                if (c != cl) {
                    w = cluster_w(sK, q, c);
                    cl = c;
                    if (3 * c >= 32 * ct) Z += w;   // count at first chunk only
                }
                float v = drow[cc] * w;
                if (j == 0) acc0 += v;
                else if (j == 1) acc1 += v;
                else acc2 += v;
            }
            __syncthreads();     // chunk consumed
        }

        // ---- attention output ----
        if (mode == 3 && p < N) {
            float invZ = 1.0f / Z;
            float t0 = acc0 * invZ, t1 = acc1 * invZ, t2 = acc2 * invZ;
            float* atp = out + 6 * (size_t)N;
            atp[3 * p + 0] = sWv[0] * t0 + sWv[1] * t1 + sWv[2] * t2;
            atp[3 * p + 1] = sWv[3] * t0 + sWv[4] * t1 + sWv[5] * t2;
            atp[3 * p + 2] = sWv[6] * t0 + sWv[7] * t1 + sWv[8] * t2;
        }
    }
}

extern "C" void kernel_launch(void* const* d_in, const int* in_sizes, int n_in,
                              void* d_out, int out_size) {
    const float* X         = (const float*)d_in[0];
    const int*   cids      = (const int*)  d_in[1];
    const float* LM        = (const float*)d_in[2];
    const float* Wq        = (const float*)d_in[3];
    const float* Wk        = (const float*)d_in[4];
    const float* Wv        = (const float*)d_in[5];
    const float* centroids = (const float*)d_in[6];

    int N = in_sizes[0] / 3;
    int mode = (out_size >= 9 * N) ? 3 : 1;

    // floats: sBv 15360 + sU 8960 + sK 512 + sWq 304 + sWv 16 = 25152
    const int SMEM = 25152 * 4;   // 100608 B -> 2 CTAs/SM (201 KB of 228)
    cudaFuncSetAttribute(csa_kernel,
                         cudaFuncAttributeMaxDynamicSharedMemorySize, SMEM);

    precompute_K_kernel<<<1, 64>>>(Wk, centroids);
    csa_kernel<<<296, TPB, SMEM>>>(X, cids, LM, Wq, Wv, (float*)d_out, N, mode);
}

// round 16
// speedup vs baseline: 1.1303x; 1.1303x over previous
#include <cuda_runtime.h>
#include <cstdint>

#define TPB 256
#define TILE 256
#define NF 10
#define NC 64
#define NCOL 192
#define DK 5
#define INV_SQRT5 0.44721359549995793f

typedef uint32_t u32;

#define SA_STR 136   // A staging stride: af loads hit 32 distinct banks
#define SB_STR 68    // B stride: B-frag loads broadcast, conflict-free
#define SD_STR 35    // D-chunk stride: readback conflict-free (3 coprime 32)

__device__ float g_K[NC * 8];   // K = posenc(centroids) @ Wk^T, stride 8

// ---------------------------------------------------------------------------
__global__ void precompute_K_kernel(const float* __restrict__ Wk,
                                    const float* __restrict__ centroids) {
    int c = threadIdx.x;
    if (c >= NC) return;
    float x0 = centroids[c * 3 + 0];
    float x1 = centroids[c * 3 + 1];
    float x2 = centroids[c * 3 + 2];
    float enc[60];
#pragma unroll
    for (int l = 0; l < NF; l++) {
        float f = (float)(1u << l);
        float s, co;
        sincosf(x0 * f, &s, &co); enc[l * 6 + 0] = s; enc[l * 6 + 3] = co;
        sincosf(x1 * f, &s, &co); enc[l * 6 + 1] = s; enc[l * 6 + 4] = co;
        sincosf(x2 * f, &s, &co); enc[l * 6 + 2] = s; enc[l * 6 + 5] = co;
    }
#pragma unroll
    for (int k = 0; k < 8; k++) {
        float a = 0.f;
        if (k < DK) {
#pragma unroll
            for (int e = 0; e < 60; e++) a += enc[e] * Wk[k * 60 + e];
        }
        g_K[c * 8 + k] = a;
    }
}

// ---------------------------------------------------------------------------
static __device__ __forceinline__ u32 to_tf32(float v) {
    u32 r;
    asm("cvt.rna.tf32.f32 %0, %1;" : "=r"(r) : "f"(v));
    return r;
}

static __device__ __forceinline__ void mma_tf32(float d[4], const u32 a[4],
                                                u32 b0, u32 b1) {
    asm volatile(
        "mma.sync.aligned.m16n8k8.row.col.f32.tf32.tf32.f32 "
        "{%0,%1,%2,%3}, {%4,%5,%6,%7}, {%8,%9}, {%0,%1,%2,%3};"
        : "+f"(d[0]), "+f"(d[1]), "+f"(d[2]), "+f"(d[3])
        : "r"(a[0]), "r"(a[1]), "r"(a[2]), "r"(a[3]), "r"(b0), "r"(b1));
}

static __device__ __forceinline__ float cluster_w(const float* sK,
                                                  const float q[DK], int c) {
    float4 k4 = *(const float4*)(sK + c * 8);
    float  k5 = sK[c * 8 + 4];
    float s = q[0] * k4.x + q[1] * k4.y + q[2] * k4.z + q[3] * k4.w + q[4] * k5;
    return __expf(s);
}

// ---------------------------------------------------------------------------
// Persistent kernel, 256 threads / 256-point tiles, 2 CTAs/SM (4 warps/SMSP).
//   rgb[256,192] = enc_tf32[256,64] @ LM_tf32[192,64]^T via mma.sync tf32.
//   D staged to smem in 32-col chunks; each thread reduces its OWN row with
//   weights recomputed from registers; Z accumulated in the SAME pass (no
//   separate score pass). kmeans exact fp32 via L2 (main output, TRADEOFF=1).
// ---------------------------------------------------------------------------
__global__ __launch_bounds__(TPB, 2) void csa_kernel(
    const float* __restrict__ X,
    const int*   __restrict__ cids,
    const float* __restrict__ LM,
    const float* __restrict__ Wq,
    const float* __restrict__ Wv,
    float* __restrict__ out,
    int N, int mode)
{
    extern __shared__ float sm[];
    float* sB  = sm;                 // [192][68] tf32 LM          13056 f
    float* sU  = sB + NCOL * SB_STR; // union: A stage [64][136] /  8960 f
                                     //        D chunk [256][35]
    float* sK  = sU + 8960;          // [64*8]                       512 f
    float* sWq = sK + NC * 8;        // [304]
    float* sWv = sWq + 304;          // [16]

    const int tid = threadIdx.x;

    // one-time loads
    for (int i = tid; i < NCOL * 64; i += TPB) {
        int n = i >> 6, k = i & 63;
        float v = (k < 60) ? LM[n * 60 + k] : 0.f;
        sB[n * SB_STR + k] = __uint_as_float(to_tf32(v));
    }
    for (int i = tid; i < NC * 8; i += TPB) sK[i] = g_K[i];
    for (int i = tid; i < DK * 60; i += TPB) sWq[i] = Wq[i];
    if (tid < 9) sWv[tid] = Wv[tid];
    __syncthreads();

    const int lane = tid & 31;
    const int warp = tid >> 5;
    const int g = lane >> 2, r4 = lane & 3;
    const int half = tid >> 7;            // 0: warps 0-3, 1: warps 4-7
    const int rb = (warp & 3) * 32 + g;   // local row base within half buffer
    const int wrow = warp * 32 + g;       // tile-local row base for D staging
    const int tiles = (N + TILE - 1) / TILE;

    for (int tile = blockIdx.x; tile < tiles; tile += gridDim.x) {
        int p = tile * TILE + tid;
        int pc = min(p, N - 1);

        // ---- prep: posenc (double-angle), q, exact kmeans via L2 ----
        float enc[64];
        {
            float x0 = X[3 * pc], x1 = X[3 * pc + 1], x2 = X[3 * pc + 2];
            float s0, c0, s1, c1, s2, c2;
            sincosf(x0, &s0, &c0);
            sincosf(x1, &s1, &c1);
            sincosf(x2, &s2, &c2);
#pragma unroll
            for (int l = 0; l < NF; l++) {
                enc[l * 6 + 0] = s0; enc[l * 6 + 1] = s1; enc[l * 6 + 2] = s2;
                enc[l * 6 + 3] = c0; enc[l * 6 + 4] = c1; enc[l * 6 + 5] = c2;
                if (l < NF - 1) {
                    float t, u;
                    t = s0 * c0; u = fmaf(c0, c0, -0.5f); s0 = t + t; c0 = u + u;
                    t = s1 * c1; u = fmaf(c1, c1, -0.5f); s1 = t + t; c1 = u + u;
                    t = s2 * c2; u = fmaf(c2, c2, -0.5f); s2 = t + t; c2 = u + u;
                }
            }
            enc[60] = enc[61] = enc[62] = enc[63] = 0.f;
        }

        float q[DK];
#pragma unroll
        for (int k = 0; k < DK; k++) {
            float a = 0.f;
            const float4* wp = (const float4*)(sWq + k * 60);
#pragma unroll
            for (int t = 0; t < 15; t++) {
                float4 w4 = wp[t];
                a += w4.x * enc[4 * t] + w4.y * enc[4 * t + 1]
                   + w4.z * enc[4 * t + 2] + w4.w * enc[4 * t + 3];
            }
            q[k] = a * INV_SQRT5;
        }

        float km0 = 0.f, km1 = 0.f, km2 = 0.f;
        {
            const float4* rp = (const float4*)(LM + 3 * (size_t)cids[pc] * 60);
#pragma unroll
            for (int t = 0; t < 15; t++) {
                float4 a = __ldg(rp + t);
                float4 b = __ldg(rp + 15 + t);
                float4 c4 = __ldg(rp + 30 + t);
                float e0 = enc[4 * t], e1 = enc[4 * t + 1];
                float e2 = enc[4 * t + 2], e3 = enc[4 * t + 3];
                km0 += a.x  * e0 + a.y  * e1 + a.z  * e2 + a.w  * e3;
                km1 += b.x  * e0 + b.y  * e1 + b.z  * e2 + b.w  * e3;
                km2 += c4.x * e0 + c4.y * e1 + c4.z * e2 + c4.w * e3;
            }
        }

        // ---- two-phase A staging + fragment preload (branch-duplicated so
        //      enc and af never overlap in any path's live range) ----
        u32 af[2][8][4];
        if (half == 0) {
            int lrow = tid;
#pragma unroll
            for (int k = 0; k < 64; k++)
                sU[k * SA_STR + lrow] = __uint_as_float(to_tf32(enc[k]));
            __syncthreads();                                  // B1
#pragma unroll
            for (int ks = 0; ks < 8; ks++) {
                int kk = ks * 8 + r4;
                af[0][ks][0] = __float_as_uint(sU[kk * SA_STR + rb]);
                af[0][ks][1] = __float_as_uint(sU[kk * SA_STR + rb + 8]);
                af[0][ks][2] = __float_as_uint(sU[(kk + 4) * SA_STR + rb]);
                af[0][ks][3] = __float_as_uint(sU[(kk + 4) * SA_STR + rb + 8]);
                af[1][ks][0] = __float_as_uint(sU[kk * SA_STR + rb + 16]);
                af[1][ks][1] = __float_as_uint(sU[kk * SA_STR + rb + 24]);
                af[1][ks][2] = __float_as_uint(sU[(kk + 4) * SA_STR + rb + 16]);
                af[1][ks][3] = __float_as_uint(sU[(kk + 4) * SA_STR + rb + 24]);
            }
            __syncthreads();                                  // B2
            __syncthreads();                                  // B3
        } else {
            __syncthreads();                                  // B1
            __syncthreads();                                  // B2
            int lrow = tid - 128;
#pragma unroll
            for (int k = 0; k < 64; k++)
                sU[k * SA_STR + lrow] = __uint_as_float(to_tf32(enc[k]));
            __syncthreads();                                  // B3
#pragma unroll
            for (int ks = 0; ks < 8; ks++) {
                int kk = ks * 8 + r4;
                af[0][ks][0] = __float_as_uint(sU[kk * SA_STR + rb]);
                af[0][ks][1] = __float_as_uint(sU[kk * SA_STR + rb + 8]);
                af[0][ks][2] = __float_as_uint(sU[(kk + 4) * SA_STR + rb]);
                af[0][ks][3] = __float_as_uint(sU[(kk + 4) * SA_STR + rb + 8]);
                af[1][ks][0] = __float_as_uint(sU[kk * SA_STR + rb + 16]);
                af[1][ks][1] = __float_as_uint(sU[kk * SA_STR + rb + 24]);
                af[1][ks][2] = __float_as_uint(sU[(kk + 4) * SA_STR + rb + 16]);
                af[1][ks][3] = __float_as_uint(sU[(kk + 4) * SA_STR + rb + 24]);
            }
        }
        __syncthreads();                                      // B4: sU -> D chunk

        // ---- MMA + chunked own-row weighted reduce (Z fused) ----
        float acc0 = 0.f, acc1 = 0.f, acc2 = 0.f, Z = 0.f;
#pragma unroll
        for (int ct = 0; ct < 6; ct++) {
#pragma unroll
            for (int ntl = 0; ntl < 4; ntl++) {
                int nt = ct * 4 + ntl;
                float d0[4] = {0.f, 0.f, 0.f, 0.f};
                float d1[4] = {0.f, 0.f, 0.f, 0.f};
                const float* bp = sB + (nt * 8 + g) * SB_STR;
#pragma unroll
                for (int ks = 0; ks < 8; ks++) {
                    u32 b0 = __float_as_uint(bp[ks * 8 + r4]);
                    u32 b1 = __float_as_uint(bp[ks * 8 + r4 + 4]);
                    mma_tf32(d0, af[0][ks], b0, b1);
                    mma_tf32(d1, af[1][ks], b0, b1);
                }
#pragma unroll
                for (int e = 0; e < 4; e++) {
                    int col = ntl * 8 + 2 * r4 + (e & 1);
                    int ro = 8 * (e >> 1);
                    sU[(wrow + ro) * SD_STR + col]      = d0[e];
                    sU[(wrow + 16 + ro) * SD_STR + col] = d1[e];
                }
            }
            __syncthreads();     // chunk staged

            const float* drow = sU + tid * SD_STR;
            float w = 0.f;
            int cl = -1;
#pragma unroll
            for (int cc = 0; cc < 32; cc++) {
                int gc = ct * 32 + cc;
                int c = gc / 3, j = gc - 3 * c;
                if (c != cl) {
                    w = cluster_w(sK, q, c);
                    cl = c;
                    if (3 * c >= 32 * ct) Z += w;   // count at first chunk only
                }
                float v = drow[cc] * w;
                if (j == 0) acc0 += v;
                else if (j == 1) acc1 += v;
                else acc2 += v;
            }
            __syncthreads();     // chunk consumed (also guards next tile's stage)
        }

        // ---- outputs ----
        if (p < N) {
            // TRADEOFF = 1.0 -> main out == kmeans_rgb exactly
            out[3 * p + 0] = km0;
            out[3 * p + 1] = km1;
            out[3 * p + 2] = km2;
            if (mode == 3) {
                float invZ = 1.0f / Z;
                float t0 = acc0 * invZ, t1 = acc1 * invZ, t2 = acc2 * invZ;
                float* kmp = out + 3 * (size_t)N;
                float* atp = out + 6 * (size_t)N;
                kmp[3 * p + 0] = km0;
                kmp[3 * p + 1] = km1;
                kmp[3 * p + 2] = km2;
                atp[3 * p + 0] = sWv[0] * t0 + sWv[1] * t1 + sWv[2] * t2;
                atp[3 * p + 1] = sWv[3] * t0 + sWv[4] * t1 + sWv[5] * t2;
                atp[3 * p + 2] = sWv[6] * t0 + sWv[7] * t1 + sWv[8] * t2;
            }
        }
    }
}

extern "C" void kernel_launch(void* const* d_in, const int* in_sizes, int n_in,
                              void* d_out, int out_size) {
    const float* X         = (const float*)d_in[0];
    const int*   cids      = (const int*)  d_in[1];
    const float* LM        = (const float*)d_in[2];
    const float* Wq        = (const float*)d_in[3];
    const float* Wk        = (const float*)d_in[4];
    const float* Wv        = (const float*)d_in[5];
    const float* centroids = (const float*)d_in[6];

    int N = in_sizes[0] / 3;
    int mode = (out_size >= 9 * N) ? 3 : 1;

    // floats: sB 13056 + sU 8960 + sK 512 + sWq 304 + sWv 16 = 22848
    const int SMEM = 22848 * 4;   // 91392 B -> 2 CTAs/SM
    cudaFuncSetAttribute(csa_kernel,
                         cudaFuncAttributeMaxDynamicSharedMemorySize, SMEM);

    precompute_K_kernel<<<1, 64>>>(Wk, centroids);
    csa_kernel<<<296, TPB, SMEM>>>(X, cids, LM, Wq, Wv, (float*)d_out, N, mode);
}

// round 17
// speedup vs baseline: 1.4949x; 1.3226x over previous
#include <cuda_runtime.h>
#include <cstdint>

#define TPB 256
#define TILE 256
#define NF 10
#define NC 64
#define NCOL 192
#define DK 5
#define INV_SQRT5 0.44721359549995793f

typedef uint32_t u32;

#define SA_STR 136   // A staging stride: af loads hit 32 distinct banks
#define SB_STR 68    // B stride: broadcast loads, conflict-free
#define SD_STR 260   // D-chunk COL-major stride: store/read banks distinct

__device__ float g_K[NC * 8];   // K = posenc(centroids) @ Wk^T, stride 8

// ---------------------------------------------------------------------------
__global__ void precompute_K_kernel(const float* __restrict__ Wk,
                                    const float* __restrict__ centroids) {
    int c = threadIdx.x;
    if (c >= NC) return;
    float x0 = centroids[c * 3 + 0];
    float x1 = centroids[c * 3 + 1];
    float x2 = centroids[c * 3 + 2];
    float enc[60];
#pragma unroll
    for (int l = 0; l < NF; l++) {
        float f = (float)(1u << l);
        float s, co;
        sincosf(x0 * f, &s, &co); enc[l * 6 + 0] = s; enc[l * 6 + 3] = co;
        sincosf(x1 * f, &s, &co); enc[l * 6 + 1] = s; enc[l * 6 + 4] = co;
        sincosf(x2 * f, &s, &co); enc[l * 6 + 2] = s; enc[l * 6 + 5] = co;
    }
#pragma unroll
    for (int k = 0; k < 8; k++) {
        float a = 0.f;
        if (k < DK) {
#pragma unroll
            for (int e = 0; e < 60; e++) a += enc[e] * Wk[k * 60 + e];
        }
        g_K[c * 8 + k] = a;
    }
}

// ---------------------------------------------------------------------------
static __device__ __forceinline__ u32 to_tf32(float v) {
    u32 r;
    asm("cvt.rna.tf32.f32 %0, %1;" : "=r"(r) : "f"(v));
    return r;
}

static __device__ __forceinline__ void mma_tf32(float d[4], const u32 a[4],
                                                u32 b0, u32 b1) {
    asm volatile(
        "mma.sync.aligned.m16n8k8.row.col.f32.tf32.tf32.f32 "
        "{%0,%1,%2,%3}, {%4,%5,%6,%7}, {%8,%9}, {%0,%1,%2,%3};"
        : "+f"(d[0]), "+f"(d[1]), "+f"(d[2]), "+f"(d[3])
        : "r"(a[0]), "r"(a[1]), "r"(a[2]), "r"(a[3]), "r"(b0), "r"(b1));
}

static __device__ __forceinline__ float cluster_w(const float* sK,
                                                  const float q[DK], int c) {
    float4 k4 = *(const float4*)(sK + c * 8);
    float  k5 = sK[c * 8 + 4];
    float s = q[0] * k4.x + q[1] * k4.y + q[2] * k4.z + q[3] * k4.w + q[4] * k5;
    return __expf(s);
}

// ---------------------------------------------------------------------------
// Persistent kernel, 256 threads / 256-point tiles, 2 CTAs/SM.
//   rgb[256,192] = enc_tf32[256,64] @ LM_tf32[192,64]^T via mma.sync tf32.
//   D staged col-major in 32-col chunks (conflict-free stores AND reads).
//   Each thread reduces its OWN row: softmax weights recomputed from regs,
//   Z fused, and kmeans_rgb extracted directly from its D row (cols 3*cid..)
//   -- no LDG gather at all.
// ---------------------------------------------------------------------------
__global__ __launch_bounds__(TPB, 2) void csa_kernel(
    const float* __restrict__ X,
    const int*   __restrict__ cids,
    const float* __restrict__ LM,
    const float* __restrict__ Wq,
    const float* __restrict__ Wv,
    float* __restrict__ out,
    int N, int mode)
{
    extern __shared__ float sm[];
    float* sB  = sm;                 // [192][68] tf32 LM          13056 f
    float* sU  = sB + NCOL * SB_STR; // union: A stage [64][136] /  8960 f
                                     //        D chunk [32][260] col-major
    float* sK  = sU + 8960;          // [64*8]                       512 f
    float* sWq = sK + NC * 8;        // [304]
    float* sWv = sWq + 304;          // [16]

    const int tid = threadIdx.x;

    // one-time loads
    for (int i = tid; i < NCOL * 64; i += TPB) {
        int n = i >> 6, k = i & 63;
        float v = (k < 60) ? LM[n * 60 + k] : 0.f;
        sB[n * SB_STR + k] = __uint_as_float(to_tf32(v));
    }
    for (int i = tid; i < NC * 8; i += TPB) sK[i] = g_K[i];
    for (int i = tid; i < DK * 60; i += TPB) sWq[i] = Wq[i];
    if (tid < 9) sWv[tid] = Wv[tid];
    __syncthreads();

    const int lane = tid & 31;
    const int warp = tid >> 5;
    const int g = lane >> 2, r4 = lane & 3;
    const int half = tid >> 7;            // 0: warps 0-3, 1: warps 4-7
    const int rb = (warp & 3) * 32 + g;   // local row base within half buffer
    const int wrow = warp * 32 + g;       // tile-local row base for D staging
    const int tiles = (N + TILE - 1) / TILE;

    for (int tile = blockIdx.x; tile < tiles; tile += gridDim.x) {
        int p = tile * TILE + tid;
        int pc = min(p, N - 1);
        int cid = cids[pc];

        // ---- prep: posenc (double-angle), q ----
        float enc[64];
        {
            float x0 = X[3 * pc], x1 = X[3 * pc + 1], x2 = X[3 * pc + 2];
            float s0, c0, s1, c1, s2, c2;
            sincosf(x0, &s0, &c0);
            sincosf(x1, &s1, &c1);
            sincosf(x2, &s2, &c2);
#pragma unroll
            for (int l = 0; l < NF; l++) {
                enc[l * 6 + 0] = s0; enc[l * 6 + 1] = s1; enc[l * 6 + 2] = s2;
                enc[l * 6 + 3] = c0; enc[l * 6 + 4] = c1; enc[l * 6 + 5] = c2;
                if (l < NF - 1) {
                    float t, u;
                    t = s0 * c0; u = fmaf(c0, c0, -0.5f); s0 = t + t; c0 = u + u;
                    t = s1 * c1; u = fmaf(c1, c1, -0.5f); s1 = t + t; c1 = u + u;
                    t = s2 * c2; u = fmaf(c2, c2, -0.5f); s2 = t + t; c2 = u + u;
                }
            }
            enc[60] = enc[61] = enc[62] = enc[63] = 0.f;
        }

        float q[DK];
#pragma unroll
        for (int k = 0; k < DK; k++) {
            float a = 0.f;
            const float4* wp = (const float4*)(sWq + k * 60);
#pragma unroll
            for (int t = 0; t < 15; t++) {
                float4 w4 = wp[t];
                a += w4.x * enc[4 * t] + w4.y * enc[4 * t + 1]
                   + w4.z * enc[4 * t + 2] + w4.w * enc[4 * t + 3];
            }
            q[k] = a * INV_SQRT5;
        }

        // ---- two-phase A staging + fragment preload (branch-duplicated so
        //      enc and af never overlap in any path's live range) ----
        u32 af[2][8][4];
        if (half == 0) {
            int lrow = tid;
#pragma unroll
            for (int k = 0; k < 64; k++)
                sU[k * SA_STR + lrow] = __uint_as_float(to_tf32(enc[k]));
            __syncthreads();                                  // B1
#pragma unroll
            for (int ks = 0; ks < 8; ks++) {
                int kk = ks * 8 + r4;
                af[0][ks][0] = __float_as_uint(sU[kk * SA_STR + rb]);
                af[0][ks][1] = __float_as_uint(sU[kk * SA_STR + rb + 8]);
                af[0][ks][2] = __float_as_uint(sU[(kk + 4) * SA_STR + rb]);
                af[0][ks][3] = __float_as_uint(sU[(kk + 4) * SA_STR + rb + 8]);
                af[1][ks][0] = __float_as_uint(sU[kk * SA_STR + rb + 16]);
                af[1][ks][1] = __float_as_uint(sU[kk * SA_STR + rb + 24]);
                af[1][ks][2] = __float_as_uint(sU[(kk + 4) * SA_STR + rb + 16]);
                af[1][ks][3] = __float_as_uint(sU[(kk + 4) * SA_STR + rb + 24]);
            }
            __syncthreads();                                  // B2
            __syncthreads();                                  // B3
        } else {
            __syncthreads();                                  // B1
            __syncthreads();                                  // B2
            int lrow = tid - 128;
#pragma unroll
            for (int k = 0; k < 64; k++)
                sU[k * SA_STR + lrow] = __uint_as_float(to_tf32(enc[k]));
            __syncthreads();                                  // B3
#pragma unroll
            for (int ks = 0; ks < 8; ks++) {
                int kk = ks * 8 + r4;
                af[0][ks][0] = __float_as_uint(sU[kk * SA_STR + rb]);
                af[0][ks][1] = __float_as_uint(sU[kk * SA_STR + rb + 8]);
                af[0][ks][2] = __float_as_uint(sU[(kk + 4) * SA_STR + rb]);
                af[0][ks][3] = __float_as_uint(sU[(kk + 4) * SA_STR + rb + 8]);
                af[1][ks][0] = __float_as_uint(sU[kk * SA_STR + rb + 16]);
                af[1][ks][1] = __float_as_uint(sU[kk * SA_STR + rb + 24]);
                af[1][ks][2] = __float_as_uint(sU[(kk + 4) * SA_STR + rb + 16]);
                af[1][ks][3] = __float_as_uint(sU[(kk + 4) * SA_STR + rb + 24]);
            }
        }
        __syncthreads();                                      // B4: sU -> D chunk

        // ---- MMA + chunked own-row weighted reduce (Z + kmeans fused) ----
        float acc0 = 0.f, acc1 = 0.f, acc2 = 0.f, Z = 0.f;
        float km0 = 0.f, km1 = 0.f, km2 = 0.f;
#pragma unroll
        for (int ct = 0; ct < 6; ct++) {
#pragma unroll
            for (int ntl = 0; ntl < 4; ntl++) {
                int nt = ct * 4 + ntl;
                float d0[4] = {0.f, 0.f, 0.f, 0.f};
                float d1[4] = {0.f, 0.f, 0.f, 0.f};
                const float* bp = sB + (nt * 8 + g) * SB_STR;
#pragma unroll
                for (int ks = 0; ks < 8; ks++) {
                    u32 b0 = __float_as_uint(bp[ks * 8 + r4]);
                    u32 b1 = __float_as_uint(bp[ks * 8 + r4 + 4]);
                    mma_tf32(d0, af[0][ks], b0, b1);
                    mma_tf32(d1, af[1][ks], b0, b1);
                }
                // col-major staging: bank = (4*col + row) % 32, all distinct
#pragma unroll
                for (int e = 0; e < 4; e++) {
                    int col = ntl * 8 + 2 * r4 + (e & 1);
                    int ro = 8 * (e >> 1);
                    sU[col * SD_STR + wrow + ro]      = d0[e];
                    sU[col * SD_STR + wrow + 16 + ro] = d1[e];
                }
            }
            __syncthreads();     // chunk staged

            float w = 0.f;
            int cl = -1;
#pragma unroll
            for (int cc = 0; cc < 32; cc++) {
                int gc = ct * 32 + cc;
                int c = gc / 3, j = gc - 3 * c;
                if (c != cl) {
                    w = cluster_w(sK, q, c);
                    cl = c;
                    if (3 * c >= 32 * ct) Z += w;   // count at first chunk only
                }
                float v = sU[cc * SD_STR + tid] * w;
                if (j == 0) acc0 += v;
                else if (j == 1) acc1 += v;
                else acc2 += v;
            }
            // kmeans = own cluster's row of the SAME GEMM result
            {
                int b0 = 3 * cid - 32 * ct;
                if (b0 >= 0 && b0 < 32)          km0 = sU[b0 * SD_STR + tid];
                if (b0 + 1 >= 0 && b0 + 1 < 32)  km1 = sU[(b0 + 1) * SD_STR + tid];
                if (b0 + 2 >= 0 && b0 + 2 < 32)  km2 = sU[(b0 + 2) * SD_STR + tid];
            }
            __syncthreads();     // chunk consumed (also guards next tile's stage)
        }

        // ---- outputs ----
        if (p < N) {
            // TRADEOFF = 1.0 -> main out == kmeans_rgb
            out[3 * p + 0] = km0;
            out[3 * p + 1] = km1;
            out[3 * p + 2] = km2;
            if (mode == 3) {
                float invZ = 1.0f / Z;
                float t0 = acc0 * invZ, t1 = acc1 * invZ, t2 = acc2 * invZ;
                float* kmp = out + 3 * (size_t)N;
                float* atp = out + 6 * (size_t)N;
                kmp[3 * p + 0] = km0;
                kmp[3 * p + 1] = km1;
                kmp[3 * p + 2] = km2;
                atp[3 * p + 0] = sWv[0] * t0 + sWv[1] * t1 + sWv[2] * t2;
                atp[3 * p + 1] = sWv[3] * t0 + sWv[4] * t1 + sWv[5] * t2;
                atp[3 * p + 2] = sWv[6] * t0 + sWv[7] * t1 + sWv[8] * t2;
            }
        }
    }
}

extern "C" void kernel_launch(void* const* d_in, const int* in_sizes, int n_in,
                              void* d_out, int out_size) {
    const float* X         = (const float*)d_in[0];
    const int*   cids      = (const int*)  d_in[1];
    const float* LM        = (const float*)d_in[2];
    const float* Wq        = (const float*)d_in[3];
    const float* Wk        = (const float*)d_in[4];
    const float* Wv        = (const float*)d_in[5];
    const float* centroids = (const float*)d_in[6];

    int N = in_sizes[0] / 3;
    int mode = (out_size >= 9 * N) ? 3 : 1;

    // floats: sB 13056 + sU 8960 + sK 512 + sWq 304 + sWv 16 = 22848
    const int SMEM = 22848 * 4;   // 91392 B -> 2 CTAs/SM
    cudaFuncSetAttribute(csa_kernel,
                         cudaFuncAttributeMaxDynamicSharedMemorySize, SMEM);

    precompute_K_kernel<<<1, 64>>>(Wk, centroids);
    csa_kernel<<<296, TPB, SMEM>>>(X, cids, LM, Wq, Wv, (float*)d_out, N, mode);
}